// round 6
// baseline (speedup 1.0000x reference)
#include <cuda_runtime.h>

typedef unsigned long long ull;
typedef unsigned int uint32;

#define TLEN 4000
#define HID  64
#define BT   2
#define NTHR 512

__device__ __forceinline__ void ffma2(ull &d, ull a, ull b) {
    asm("fma.rn.f32x2 %0, %1, %2, %0;" : "+l"(d) : "l"(a), "l"(b));
}
__device__ __forceinline__ float2 unpack2(ull v) {
    float2 r;
    asm("mov.b64 {%0, %1}, %2;" : "=f"(r.x), "=f"(r.y) : "l"(v));
    return r;
}
__device__ __forceinline__ ull pack2(float x, float y) {
    ull r;
    asm("mov.b64 %0, {%1, %2};" : "=l"(r) : "f"(x), "f"(y));
    return r;
}
__device__ __forceinline__ float tanha(float x) {
    float r;
    asm("tanh.approx.f32 %0, %1;" : "=f"(r) : "f"(x));
    return r;
}
__device__ __forceinline__ float fsigmoid(float x) {
    return fmaf(tanha(0.5f * x), 0.5f, 0.5f);
}
// Reduce a packed f32x2 accumulator with the K-half partner (lane ^ 16).
__device__ __forceinline__ float reduce_kpair(ull acc) {
    uint32 lo, hi;
    asm("mov.b64 {%0, %1}, %2;" : "=r"(lo), "=r"(hi) : "l"(acc));
    lo = __shfl_xor_sync(0xffffffffu, lo, 16);
    hi = __shfl_xor_sync(0xffffffffu, hi, 16);
    ull other;
    asm("mov.b64 %0, {%1, %2};" : "=l"(other) : "r"(lo), "r"(hi));
    ull sum;
    asm("add.rn.f32x2 %0, %1, %2;" : "=l"(sum) : "l"(acc), "l"(other));
    float2 f = unpack2(sum);
    return f.x + f.y;
}

__global__ void __launch_bounds__(NTHR, 1)
lstm2_ks(const float* __restrict__ x,
         const float* __restrict__ W_ih0,
         const float* __restrict__ W_hh0,
         const float* __restrict__ b_ih0,
         const float* __restrict__ b_hh0,
         const float* __restrict__ W_ih1,
         const float* __restrict__ W_hh1,
         const float* __restrict__ b_ih1,
         const float* __restrict__ b_hh1,
         const float* __restrict__ W_fc,
         const float* __restrict__ b_fc,
         float* __restrict__ out)
{
    __shared__ __align__(16) float sh_x[BT * TLEN];       // 32 KB staged input
    __shared__ __align__(16) float sh_h[2][BT][2 * HID];  // dbl-buf [h0|h1]
    __shared__ __align__(16) float sh_s[16][4][4][4];     // [warp][gate][a][combo]

    const int tid   = threadIdx.x;
    const int v     = tid >> 5;          // warp 0..15
    const int l     = tid & 31;
    const int a     = l & 3;             // unit-low
    const int g     = (l >> 2) & 3;      // gate (i,f,g,o) AND pointwise combo
    const int kh    = l >> 4;            // K-half 0/1
    const int u     = 4 * v + a;         // unit 0..63
    const int row   = 64 * g + u;        // gate row this (lane-pair) owns
    const int bbase = blockIdx.x * BT;

    // Stage x (two contiguous batch rows)
    {
        const float4* xg = (const float4*)(x + (size_t)bbase * TLEN);
        float4* xs = (float4*)sh_x;
        for (int i = tid; i < BT * TLEN / 4; i += NTHR) xs[i] = xg[i];
    }
    ((float*)sh_h)[tid] = 0.0f;          // 512 floats = both slots

    // Per-thread HALF-K weight rows in registers (packed f32 pairs).
    ull wA[16], wI[16], wH[16];          // 48 ull = 96 regs
    {
        const ulonglong2* p = (const ulonglong2*)(W_hh0 + row * HID + kh * 32);
        #pragma unroll
        for (int t = 0; t < 8; t++) { ulonglong2 q_ = p[t]; wA[2*t] = q_.x; wA[2*t+1] = q_.y; }
        p = (const ulonglong2*)(W_ih1 + row * HID + kh * 32);
        #pragma unroll
        for (int t = 0; t < 8; t++) { ulonglong2 q_ = p[t]; wI[2*t] = q_.x; wI[2*t+1] = q_.y; }
        p = (const ulonglong2*)(W_hh1 + row * HID + kh * 32);
        #pragma unroll
        for (int t = 0; t < 8; t++) { ulonglong2 q_ = p[t]; wH[2*t] = q_.x; wH[2*t+1] = q_.y; }
    }
    const float wx    = W_ih0[row];
    const float biasA = b_ih0[row] + b_hh0[row];
    const float biasB = b_ih1[row] + b_hh1[row];

    // Pointwise combo for this lane: g -> (layer Lq, batch bq), unit u.
    const int Lq = g >> 1;
    const int bq = g & 1;
    const int hoff = Lq * HID + u;
    float c = 0.0f;

    __syncthreads();

    // Iter k: half-dots gA(k) + gB(k-1), bfly-16 reduction, warp-local gate
    // exchange, pointwise -> h0(k), h1(k-1). ONE CTA barrier per step.
    for (int k = 0; k <= TLEN; ++k) {
        const int rs = (k + 1) & 1;
        const int ws = k & 1;
        // ---- half-K matvec ----
        float gv0, gv1, gv2, gv3;
        {
            const int xk = (k < TLEN) ? k : TLEN - 1;
            ull aA0, aA1, aB0, aB1;
            if (kh == 0) {
                aA0 = pack2(fmaf(sh_x[xk], wx, biasA), 0.0f);
                aA1 = pack2(fmaf(sh_x[TLEN + xk], wx, biasA), 0.0f);
                aB0 = pack2(biasB, 0.0f);
                aB1 = aB0;                       // FIX: batch1 gets biasB too
            } else {
                aA0 = 0ull; aA1 = 0ull; aB0 = 0ull; aB1 = 0ull;
            }

            const ulonglong2* h0b0 = (const ulonglong2*)&sh_h[rs][0][kh * 32];
            const ulonglong2* h0b1 = (const ulonglong2*)&sh_h[rs][1][kh * 32];
            const ulonglong2* h1b0 = (const ulonglong2*)&sh_h[rs][0][HID + kh * 32];
            const ulonglong2* h1b1 = (const ulonglong2*)&sh_h[rs][1][HID + kh * 32];

            #pragma unroll
            for (int t = 0; t < 8; t++) {        // h0-half feeds wA and wI
                ulonglong2 v0 = h0b0[t], v1 = h0b1[t];
                ffma2(aA0, wA[2*t],   v0.x);
                ffma2(aA1, wA[2*t],   v1.x);
                ffma2(aB0, wI[2*t],   v0.x);
                ffma2(aB1, wI[2*t],   v1.x);
                ffma2(aA0, wA[2*t+1], v0.y);
                ffma2(aA1, wA[2*t+1], v1.y);
                ffma2(aB0, wI[2*t+1], v0.y);
                ffma2(aB1, wI[2*t+1], v1.y);
            }
            #pragma unroll
            for (int t = 0; t < 8; t++) {        // h1-half feeds wH
                ulonglong2 v0 = h1b0[t], v1 = h1b1[t];
                ffma2(aB0, wH[2*t],   v0.x);
                ffma2(aB1, wH[2*t],   v1.x);
                ffma2(aB0, wH[2*t+1], v0.y);
                ffma2(aB1, wH[2*t+1], v1.y);
            }
            gv0 = reduce_kpair(aA0);   // gA batch0
            gv1 = reduce_kpair(aA1);   // gA batch1
            gv2 = reduce_kpair(aB0);   // gB batch0
            gv3 = reduce_kpair(aB1);   // gB batch1
        }
        if (kh == 0)
            *(float4*)&sh_s[v][g][a][0] = make_float4(gv0, gv1, gv2, gv3);
        __syncwarp();
        // ---- pointwise: lane -> (combo g, unit u); both K-halves redundant ----
        {
            const bool active = (g < 2) ? (k < TLEN) : (k >= 1);
            float g_i = sh_s[v][0][a][g];
            float g_f = sh_s[v][1][a][g];
            float g_c = sh_s[v][2][a][g];
            float g_o = sh_s[v][3][a][g];
            float iv = fsigmoid(g_i), fv = fsigmoid(g_f), ov = fsigmoid(g_o);
            float cv = tanha(g_c);
            float cn = fmaf(fv, c, iv * cv);
            if (active) {
                c = cn;
                if (kh == 0) sh_h[ws][bq][hoff] = ov * tanha(c);
            }
        }
        __syncthreads();
    }

    // ---- FC head on final h1 (written at k=4000 -> slot 0) ----
    if (tid < 256) {
        const int e  = tid & 127;
        const int bb = tid >> 7;
        float acc = b_fc[e];
        const float* wr = W_fc + e * HID;
        const float* hv = &sh_h[0][bb][HID];
        #pragma unroll
        for (int t = 0; t < HID; t += 4) {
            acc = fmaf(wr[t],     hv[t],     acc);
            acc = fmaf(wr[t + 1], hv[t + 1], acc);
            acc = fmaf(wr[t + 2], hv[t + 2], acc);
            acc = fmaf(wr[t + 3], hv[t + 3], acc);
        }
        out[(size_t)(bbase + bb) * 128 + e] = acc;
    }
}

extern "C" void kernel_launch(void* const* d_in, const int* in_sizes, int n_in,
                              void* d_out, int out_size) {
    (void)in_sizes; (void)n_in; (void)out_size;
    lstm2_ks<<<128, NTHR>>>(
        (const float*)d_in[0],   // x
        (const float*)d_in[1],   // W_ih0
        (const float*)d_in[2],   // W_hh0
        (const float*)d_in[3],   // b_ih0
        (const float*)d_in[4],   // b_hh0
        (const float*)d_in[5],   // W_ih1
        (const float*)d_in[6],   // W_hh1
        (const float*)d_in[7],   // b_ih1
        (const float*)d_in[8],   // b_hh1
        (const float*)d_in[9],   // W_fc
        (const float*)d_in[10],  // b_fc
        (float*)d_out);
}

// round 7
// speedup vs baseline: 1.0177x; 1.0177x over previous
#include <cuda_runtime.h>

typedef unsigned long long ull;

#define TLEN 4000
#define HID  64
#define BT   2
#define NTHR 512

__device__ __forceinline__ void ffma2(ull &d, ull a, ull b) {
    asm("fma.rn.f32x2 %0, %1, %2, %0;" : "+l"(d) : "l"(a), "l"(b));
}
__device__ __forceinline__ float2 unpack2(ull v) {
    float2 r;
    asm("mov.b64 {%0, %1}, %2;" : "=f"(r.x), "=f"(r.y) : "l"(v));
    return r;
}
__device__ __forceinline__ ull pack2(float x, float y) {
    ull r;
    asm("mov.b64 %0, {%1, %2};" : "=l"(r) : "f"(x), "f"(y));
    return r;
}
__device__ __forceinline__ float tanha(float x) {
    float r;
    asm("tanh.approx.f32 %0, %1;" : "=f"(r) : "f"(x));
    return r;
}
__device__ __forceinline__ float fsigmoid(float x) {
    return fmaf(tanha(0.5f * x), 0.5f, 0.5f);
}
__device__ __forceinline__ float hsum(ull acc) {
    float2 f = unpack2(acc);
    return f.x + f.y;
}

__global__ void __launch_bounds__(NTHR, 1)
lstm2_ks2(const float* __restrict__ x,
          const float* __restrict__ W_ih0,
          const float* __restrict__ W_hh0,
          const float* __restrict__ b_ih0,
          const float* __restrict__ b_hh0,
          const float* __restrict__ W_ih1,
          const float* __restrict__ W_hh1,
          const float* __restrict__ b_ih1,
          const float* __restrict__ b_hh1,
          const float* __restrict__ W_fc,
          const float* __restrict__ b_fc,
          float* __restrict__ out)
{
    __shared__ __align__(16) float  sh_x[BT * TLEN];       // 32 KB staged input
    __shared__ __align__(16) float  sh_h[2][BT][2 * HID];  // dbl-buf [h0|h1]
    __shared__ __align__(16) float4 sh_s[16][4][4][2];     // [warp][gate][a][kh] -> 4 combos

    const int tid   = threadIdx.x;
    const int v     = tid >> 5;          // warp 0..15
    const int l     = tid & 31;
    const int a     = l & 3;             // unit-low
    const int g     = (l >> 2) & 3;      // gate (i,f,g,o) AND pointwise combo
    const int kh    = l >> 4;            // K-half 0/1
    const int u     = 4 * v + a;         // unit 0..63
    const int row   = 64 * g + u;        // gate row this (lane-pair) owns
    const int bbase = blockIdx.x * BT;

    // Stage x (two contiguous batch rows)
    {
        const float4* xg = (const float4*)(x + (size_t)bbase * TLEN);
        float4* xs = (float4*)sh_x;
        for (int i = tid; i < BT * TLEN / 4; i += NTHR) xs[i] = xg[i];
    }
    ((float*)sh_h)[tid] = 0.0f;          // 512 floats = both slots

    // Per-thread HALF-K weight rows in registers (packed f32 pairs).
    ull wA[16], wI[16], wH[16];          // 48 ull = 96 regs
    {
        const ulonglong2* p = (const ulonglong2*)(W_hh0 + row * HID + kh * 32);
        #pragma unroll
        for (int t = 0; t < 8; t++) { ulonglong2 q_ = p[t]; wA[2*t] = q_.x; wA[2*t+1] = q_.y; }
        p = (const ulonglong2*)(W_ih1 + row * HID + kh * 32);
        #pragma unroll
        for (int t = 0; t < 8; t++) { ulonglong2 q_ = p[t]; wI[2*t] = q_.x; wI[2*t+1] = q_.y; }
        p = (const ulonglong2*)(W_hh1 + row * HID + kh * 32);
        #pragma unroll
        for (int t = 0; t < 8; t++) { ulonglong2 q_ = p[t]; wH[2*t] = q_.x; wH[2*t+1] = q_.y; }
    }
    const float wx    = W_ih0[row];
    const float biasA = b_ih0[row] + b_hh0[row];
    const float biasB = b_ih1[row] + b_hh1[row];

    // Pointwise combo for this lane: g -> (layer Lq, batch bq), unit u.
    const int Lq = g >> 1;
    const int bq = g & 1;
    const int hoff = Lq * HID + u;
    // Per-warp float view of the gate scratch for the reader side.
    const float* sp = (const float*)&sh_s[v][0][0][0];
    float c = 0.0f;

    __syncthreads();

    // Iter k: half-dots gA(k) + gB(k-1); K-pair reduction THROUGH SMEM
    // (no shuffles); warp-local pointwise -> h0(k), h1(k-1).
    // ONE CTA barrier per step.
    for (int k = 0; k <= TLEN; ++k) {
        const int rs = (k + 1) & 1;
        const int ws = k & 1;
        // ---- half-K matvec ----
        {
            const int xk = (k < TLEN) ? k : TLEN - 1;
            ull aA0, aA1, aB0, aB1;
            if (kh == 0) {
                aA0 = pack2(fmaf(sh_x[xk], wx, biasA), 0.0f);
                aA1 = pack2(fmaf(sh_x[TLEN + xk], wx, biasA), 0.0f);
                aB0 = pack2(biasB, 0.0f);
                aB1 = aB0;
            } else {
                aA0 = 0ull; aA1 = 0ull; aB0 = 0ull; aB1 = 0ull;
            }

            const ulonglong2* h0b0 = (const ulonglong2*)&sh_h[rs][0][kh * 32];
            const ulonglong2* h0b1 = (const ulonglong2*)&sh_h[rs][1][kh * 32];
            const ulonglong2* h1b0 = (const ulonglong2*)&sh_h[rs][0][HID + kh * 32];
            const ulonglong2* h1b1 = (const ulonglong2*)&sh_h[rs][1][HID + kh * 32];

            #pragma unroll
            for (int t = 0; t < 8; t++) {        // h0-half feeds wA and wI
                ulonglong2 v0 = h0b0[t], v1 = h0b1[t];
                ffma2(aA0, wA[2*t],   v0.x);
                ffma2(aA1, wA[2*t],   v1.x);
                ffma2(aB0, wI[2*t],   v0.x);
                ffma2(aB1, wI[2*t],   v1.x);
                ffma2(aA0, wA[2*t+1], v0.y);
                ffma2(aA1, wA[2*t+1], v1.y);
                ffma2(aB0, wI[2*t+1], v0.y);
                ffma2(aB1, wI[2*t+1], v1.y);
            }
            #pragma unroll
            for (int t = 0; t < 8; t++) {        // h1-half feeds wH
                ulonglong2 v0 = h1b0[t], v1 = h1b1[t];
                ffma2(aB0, wH[2*t],   v0.x);
                ffma2(aB1, wH[2*t],   v1.x);
                ffma2(aB0, wH[2*t+1], v0.y);
                ffma2(aB1, wH[2*t+1], v1.y);
            }
            // Store this K-half's 4 partial sums (one STS.128).
            sh_s[v][g][a][kh] = make_float4(hsum(aA0), hsum(aA1),
                                            hsum(aB0), hsum(aB1));
        }
        __syncwarp();
        // ---- pointwise: lane -> (combo g, unit u); add the two K-halves ----
        {
            const bool active = (g < 2) ? (k < TLEN) : (k >= 1);
            // float layout: idx = ((G*4 + a)*2 + kh)*4 + combo
            float g_i = sp[(0*4 + a)*8 + g] + sp[(0*4 + a)*8 + 4 + g];
            float g_f = sp[(1*4 + a)*8 + g] + sp[(1*4 + a)*8 + 4 + g];
            float g_c = sp[(2*4 + a)*8 + g] + sp[(2*4 + a)*8 + 4 + g];
            float g_o = sp[(3*4 + a)*8 + g] + sp[(3*4 + a)*8 + 4 + g];
            float iv = fsigmoid(g_i), fv = fsigmoid(g_f), ov = fsigmoid(g_o);
            float cv = tanha(g_c);
            float cn = fmaf(fv, c, iv * cv);
            if (active) {
                c = cn;
                if (kh == 0) sh_h[ws][bq][hoff] = ov * tanha(c);
            }
        }
        __syncthreads();
    }

    // ---- FC head on final h1 (written at k=4000 -> slot 0) ----
    if (tid < 256) {
        const int e  = tid & 127;
        const int bb = tid >> 7;
        float acc = b_fc[e];
        const float* wr = W_fc + e * HID;
        const float* hv = &sh_h[0][bb][HID];
        #pragma unroll
        for (int t = 0; t < HID; t += 4) {
            acc = fmaf(wr[t],     hv[t],     acc);
            acc = fmaf(wr[t + 1], hv[t + 1], acc);
            acc = fmaf(wr[t + 2], hv[t + 2], acc);
            acc = fmaf(wr[t + 3], hv[t + 3], acc);
        }
        out[(size_t)(bbase + bb) * 128 + e] = acc;
    }
}

extern "C" void kernel_launch(void* const* d_in, const int* in_sizes, int n_in,
                              void* d_out, int out_size) {
    (void)in_sizes; (void)n_in; (void)out_size;
    lstm2_ks2<<<128, NTHR>>>(
        (const float*)d_in[0],   // x
        (const float*)d_in[1],   // W_ih0
        (const float*)d_in[2],   // W_hh0
        (const float*)d_in[3],   // b_ih0
        (const float*)d_in[4],   // b_hh0
        (const float*)d_in[5],   // W_ih1
        (const float*)d_in[6],   // W_hh1
        (const float*)d_in[7],   // b_ih1
        (const float*)d_in[8],   // b_hh1
        (const float*)d_in[9],   // W_fc
        (const float*)d_in[10],  // b_fc
        (float*)d_out);
}